// round 4
// baseline (speedup 1.0000x reference)
#include <cuda_runtime.h>
#include <cstdint>

typedef unsigned long long u64;
typedef unsigned int u32;

__device__ __forceinline__ u64 ffma2(u64 a, u64 b, u64 c) {
    u64 d; asm("fma.rn.f32x2 %0, %1, %2, %3;" : "=l"(d) : "l"(a), "l"(b), "l"(c)); return d;
}
__device__ __forceinline__ u64 pack2(float x, float y) {
    u64 r; asm("mov.b64 %0, {%1, %2};" : "=l"(r) : "f"(x), "f"(y)); return r;
}
__device__ __forceinline__ float2 unpack2(u64 v) {
    float2 r; asm("mov.b64 {%0, %1}, %2;" : "=f"(r.x), "=f"(r.y) : "l"(v)); return r;
}
__device__ __forceinline__ float clip1(float v) { return fminf(fmaxf(v, -1.0f), 1.0f); }
__device__ __forceinline__ u64 shflx64(u64 v, int m) {
    u32 lo = (u32)v, hi = (u32)(v >> 32);
    lo = __shfl_xor_sync(0xffffffffu, lo, m);
    hi = __shfl_xor_sync(0xffffffffu, hi, m);
    return ((u64)hi << 32) | (u64)lo;
}

constexpr int NWARP    = 4;
constexpr int NTHREADS = 128;
constexpr int ROWS_W   = 16;         // rows per warp (lane pair per row)
constexpr int INSTRIDE = 386;        // even; 386 mod 32 = 2 -> r*stride hits 16 distinct banks
constexpr int VSTRIDE  = 38;

constexpr int SW1_N = 27 * 8;        // u64 [fp][o]
constexpr int SW2_N = 4 * 8;         // u64 [fp][o]
constexpr int E1T_N = 19 * 16;       // u64 [fp][o]
constexpr int E2T_N = 8 * 16;        // u64 [fp][o]
constexpr int WU_N  = SW1_N + SW2_N + E1T_N + E2T_N;
constexpr int IN_N  = NWARP * ROWS_W * INSTRIDE;
constexpr int VB_N  = NWARP * ROWS_W * VSTRIDE;
constexpr size_t SMEM_BYTES = (size_t)WU_N * 8 + (size_t)(IN_N + VB_N) * 4;

__global__ __launch_bounds__(NTHREADS, 2)
void lila_kernel(const float* __restrict__ inp,
                 const float* __restrict__ W1, const float* __restrict__ b1,
                 const float* __restrict__ W2, const float* __restrict__ b2,
                 const float* __restrict__ W3, const float* __restrict__ b3,
                 const float* __restrict__ E1, const float* __restrict__ c1,
                 const float* __restrict__ E2, const float* __restrict__ c2,
                 const float* __restrict__ E3, const float* __restrict__ c3,
                 float* __restrict__ out, int B)
{
    extern __shared__ __align__(16) char smem_raw[];
    u64*   SW1 = reinterpret_cast<u64*>(smem_raw);
    u64*   SW2 = SW1 + SW1_N;
    u64*   E1T = SW2 + SW2_N;
    u64*   E2T = E1T + E1T_N;
    float* IN  = reinterpret_cast<float*>(E2T + E2T_N);
    float* VB  = IN + IN_N;

    const int tid  = threadIdx.x;
    const int lane = tid & 31;
    const int warp = tid >> 5;
    const int r    = lane >> 1;      // row within warp (0..15)
    const int h    = lane & 1;       // output half

    // ---- stage weights ----
    for (int i = tid; i < SW1_N; i += NTHREADS) {
        int fp = i >> 3, o = i & 7;
        SW1[i] = pack2(W1[(2 * fp) * 8 + o], W1[(2 * fp + 1) * 8 + o]);
    }
    for (int i = tid; i < SW2_N; i += NTHREADS) {
        int fp = i >> 3, o = i & 7;
        SW2[i] = pack2(W2[(2 * fp) * 8 + o], W2[(2 * fp + 1) * 8 + o]);
    }
    for (int i = tid; i < E1T_N; i += NTHREADS) {
        int fp = i >> 4, o = i & 15;
        E1T[i] = (fp < 18) ? pack2(E1[(2 * fp) * 16 + o], E1[(2 * fp + 1) * 16 + o])
                           : pack2(E1[36 * 16 + o], 0.0f);
    }
    for (int i = tid; i < E2T_N; i += NTHREADS) {
        int fp = i >> 4, o = i & 15;
        E2T[i] = pack2(E2[(2 * fp) * 16 + o], E2[(2 * fp + 1) * 16 + o]);
    }

    // ---- per-lane register constants ----
    float b1f[4], b2f[4];
#pragma unroll
    for (int k = 0; k < 4; k++) {
        b1f[k] = __ldg(b1 + 4 * h + k);
        b2f[k] = __ldg(b2 + 4 * h + k);
    }
    u64 w3p0 = pack2(__ldg(W3 + 4 * h + 0), __ldg(W3 + 4 * h + 1));
    u64 w3p1 = pack2(__ldg(W3 + 4 * h + 2), __ldg(W3 + 4 * h + 3));
    const float b3s = __ldg(b3);
    const float c3s = __ldg(c3);

    float c1f[8], c2f[8];
#pragma unroll
    for (int k = 0; k < 8; k++) {
        c1f[k] = __ldg(c1 + 8 * h + k);
        c2f[k] = __ldg(c2 + 8 * h + k);
    }
    u64 e3p[4];
#pragma unroll
    for (int t = 0; t < 4; t++)
        e3p[t] = pack2(__ldg(E3 + 8 * h + 2 * t), __ldg(E3 + 8 * h + 2 * t + 1));

    __syncthreads();

    float* warp_in = IN + warp * (ROWS_W * INSTRIDE);
    float* warp_vb = VB + warp * (ROWS_W * VSTRIDE);
    float* lane_in = warp_in + r * INSTRIDE;
    float* lane_vb = warp_vb + r * VSTRIDE;

    const ulonglong2* SW1v = reinterpret_cast<const ulonglong2*>(SW1);
    const ulonglong2* SW2v = reinterpret_cast<const ulonglong2*>(SW2);
    const ulonglong2* E1Tv = reinterpret_cast<const ulonglong2*>(E1T);
    const ulonglong2* E2Tv = reinterpret_cast<const ulonglong2*>(E2T);

    const int wg      = blockIdx.x * NWARP + warp;
    const int rowstep = gridDim.x * NWARP * ROWS_W;

    for (int rb = wg * ROWS_W; rb < B; rb += rowstep) {
        __syncwarp();

        // ---- stage 16 rows (coalesced LDG.32 / conflict-free STS.32) ----
#pragma unroll 1
        for (int rr = 0; rr < ROWS_W; rr++) {
            int row = rb + rr;
            float* dst = warp_in + rr * INSTRIDE;
            if (row < B) {
                const float* src = inp + (size_t)row * 385;
#pragma unroll
                for (int k = 0; k < 12; k++)
                    dst[lane + 32 * k] = __ldg(src + lane + 32 * k);
                if (lane == 0) {
                    float cv = __ldg(src + 384);
                    warp_vb[rr * VSTRIDE + 36] = cv;
                    warp_vb[rr * VSTRIDE + 37] = 0.0f;
                }
            } else {
#pragma unroll
                for (int k = 0; k < 12; k++)
                    dst[lane + 32 * k] = 0.0f;
                if (lane == 0) {
                    warp_vb[rr * VSTRIDE + 36] = 0.0f;
                    warp_vb[rr * VSTRIDE + 37] = 0.0f;
                }
            }
        }
        __syncwarp();

        // ---- 3 passes: 12 patches per lane-pair per pass (x = 2*li, 2*li+1) ----
#pragma unroll 1
        for (int li = 0; li < 3; li++) {
            const float* pli = lane_in + li * 96;   // x = 2*li base

            u64 acc[12][4];
#pragma unroll
            for (int j = 0; j < 12; j++)
#pragma unroll
                for (int q = 0; q < 4; q++) acc[j][q] = 0ull;

            // layer 1: 27 feature-pairs, 12 patches
#pragma unroll 1
            for (int c = 0; c < 9; c++) {
                const int off = (c / 3) * 48 + (c % 3) * 6;
#pragma unroll
                for (int j3 = 0; j3 < 3; j3++) {
                    const int fp = 3 * c + j3;
                    const int coff = off + 2 * j3;
                    ulonglong2 wa = SW1v[fp * 4 + 2 * h];
                    ulonglong2 wb = SW1v[fp * 4 + 2 * h + 1];
                    u64 iv[12];
#pragma unroll
                    for (int j = 0; j < 12; j++) {
                        const int poff = (j / 6) * 48 + (j % 6) * 6;
                        iv[j] = *reinterpret_cast<const u64*>(pli + poff + coff);
                    }
#pragma unroll
                    for (int j = 0; j < 12; j++) {
                        acc[j][0] = ffma2(iv[j], wa.x, acc[j][0]);
                        acc[j][1] = ffma2(iv[j], wa.y, acc[j][1]);
                        acc[j][2] = ffma2(iv[j], wb.x, acc[j][2]);
                        acc[j][3] = ffma2(iv[j], wb.y, acc[j][3]);
                    }
                }
            }

            // load W2 half for this lane (held in regs over 12 patches)
            ulonglong2 w2a[4], w2b[4];
#pragma unroll
            for (int fp = 0; fp < 4; fp++) {
                w2a[fp] = SW2v[fp * 4 + 2 * h];
                w2b[fp] = SW2v[fp * 4 + 2 * h + 1];
            }

            // epilogue + L2 + L3 per patch
#pragma unroll
            for (int j = 0; j < 12; j++) {
                float2 f0 = unpack2(acc[j][0]);
                float2 f1 = unpack2(acc[j][1]);
                float2 f2 = unpack2(acc[j][2]);
                float2 f3 = unpack2(acc[j][3]);
                u64 m0 = pack2(clip1(f0.x + f0.y + b1f[0]), clip1(f1.x + f1.y + b1f[1]));
                u64 m1 = pack2(clip1(f2.x + f2.y + b1f[2]), clip1(f3.x + f3.y + b1f[3]));
                u64 p0 = shflx64(m0, 1);
                u64 p1 = shflx64(m1, 1);
                u64 x0 = h ? p0 : m0, x1 = h ? p1 : m1;
                u64 x2 = h ? m0 : p0, x3 = h ? m1 : p1;

                u64 a0 = 0ull, a1 = 0ull, a2 = 0ull, a3 = 0ull;
                a0 = ffma2(x0, w2a[0].x, a0); a1 = ffma2(x0, w2a[0].y, a1);
                a2 = ffma2(x0, w2b[0].x, a2); a3 = ffma2(x0, w2b[0].y, a3);
                a0 = ffma2(x1, w2a[1].x, a0); a1 = ffma2(x1, w2a[1].y, a1);
                a2 = ffma2(x1, w2b[1].x, a2); a3 = ffma2(x1, w2b[1].y, a3);
                a0 = ffma2(x2, w2a[2].x, a0); a1 = ffma2(x2, w2a[2].y, a1);
                a2 = ffma2(x2, w2b[2].x, a2); a3 = ffma2(x2, w2b[2].y, a3);
                a0 = ffma2(x3, w2a[3].x, a0); a1 = ffma2(x3, w2a[3].y, a1);
                a2 = ffma2(x3, w2b[3].x, a2); a3 = ffma2(x3, w2b[3].y, a3);

                float2 g0 = unpack2(a0), g1 = unpack2(a1);
                float2 g2 = unpack2(a2), g3 = unpack2(a3);
                u64 n0 = pack2(clip1(g0.x + g0.y + b2f[0]), clip1(g1.x + g1.y + b2f[1]));
                u64 n1 = pack2(clip1(g2.x + g2.y + b2f[2]), clip1(g3.x + g3.y + b2f[3]));

                u64 s = ffma2(n0, w3p0, ffma2(n1, w3p1, 0ull));
                float2 sf = unpack2(s);
                float part = sf.x + sf.y;
                float tot = part + __shfl_xor_sync(0xffffffffu, part, 1);
                if (h == 0) {
                    const int p = li * 12 + j;   // x = 2li + j/6, y = j%6
                    lane_vb[p] = clip1(tot + b3s);
                }
            }
        }
        __syncwarp();

        // ---- head: lane = (row r, out-half h); vision[37] -> 16 -> 16 -> 1 ----
        u64 g[8];
#pragma unroll
        for (int k = 0; k < 8; k++) g[k] = 0ull;
#pragma unroll
        for (int fp = 0; fp < 19; fp++) {
            u64 iv = *reinterpret_cast<const u64*>(lane_vb + 2 * fp);
#pragma unroll
            for (int t = 0; t < 4; t++) {
                ulonglong2 wv = E1Tv[fp * 8 + 4 * h + t];
                g[2 * t]     = ffma2(iv, wv.x, g[2 * t]);
                g[2 * t + 1] = ffma2(iv, wv.y, g[2 * t + 1]);
            }
        }
        float gv[8];
#pragma unroll
        for (int k = 0; k < 8; k++) {
            float2 f = unpack2(g[k]);
            gv[k] = clip1(f.x + f.y + c1f[k]);
        }
        u64 q0 = pack2(gv[0], gv[1]), q1 = pack2(gv[2], gv[3]);
        u64 q2 = pack2(gv[4], gv[5]), q3 = pack2(gv[6], gv[7]);
        u64 s0 = shflx64(q0, 1), s1 = shflx64(q1, 1);
        u64 s2 = shflx64(q2, 1), s3 = shflx64(q3, 1);
        u64 z[8];
        z[0] = h ? s0 : q0; z[1] = h ? s1 : q1;
        z[2] = h ? s2 : q2; z[3] = h ? s3 : q3;
        z[4] = h ? q0 : s0; z[5] = h ? q1 : s1;
        z[6] = h ? q2 : s2; z[7] = h ? q3 : s3;

        u64 d[8];
#pragma unroll
        for (int k = 0; k < 8; k++) d[k] = 0ull;
#pragma unroll
        for (int fp = 0; fp < 8; fp++) {
#pragma unroll
            for (int t = 0; t < 4; t++) {
                ulonglong2 wv = E2Tv[fp * 8 + 4 * h + t];
                d[2 * t]     = ffma2(z[fp], wv.x, d[2 * t]);
                d[2 * t + 1] = ffma2(z[fp], wv.y, d[2 * t + 1]);
            }
        }
        float dv[8];
#pragma unroll
        for (int k = 0; k < 8; k++) {
            float2 f = unpack2(d[k]);
            dv[k] = clip1(f.x + f.y + c2f[k]);
        }
        u64 s = ffma2(pack2(dv[0], dv[1]), e3p[0],
                ffma2(pack2(dv[2], dv[3]), e3p[1],
                ffma2(pack2(dv[4], dv[5]), e3p[2],
                ffma2(pack2(dv[6], dv[7]), e3p[3], 0ull))));
        float2 sf = unpack2(s);
        float part = sf.x + sf.y;
        float tot = part + __shfl_xor_sync(0xffffffffu, part, 1);
        int row = rb + r;
        if (h == 0 && row < B) out[row] = clip1(tot + c3s);
    }
}

extern "C" void kernel_launch(void* const* d_in, const int* in_sizes, int n_in,
                              void* d_out, int out_size)
{
    const float* inp = (const float*)d_in[0];
    const float* W1  = (const float*)d_in[1];
    const float* b1  = (const float*)d_in[2];
    const float* W2  = (const float*)d_in[3];
    const float* b2  = (const float*)d_in[4];
    const float* W3  = (const float*)d_in[5];
    const float* b3  = (const float*)d_in[6];
    const float* E1  = (const float*)d_in[7];
    const float* c1  = (const float*)d_in[8];
    const float* E2  = (const float*)d_in[9];
    const float* c2  = (const float*)d_in[10];
    const float* E3  = (const float*)d_in[11];
    const float* c3  = (const float*)d_in[12];

    int B = in_sizes[0] / 385;

    cudaFuncSetAttribute(lila_kernel, cudaFuncAttributeMaxDynamicSharedMemorySize,
                         (int)SMEM_BYTES);

    lila_kernel<<<296, NTHREADS, SMEM_BYTES>>>(inp, W1, b1, W2, b2, W3, b3,
                                               E1, c1, E2, c2, E3, c3,
                                               (float*)d_out, B);
}